// round 2
// baseline (speedup 1.0000x reference)
#include <cuda_runtime.h>

// ---------------------------------------------------------------------------
// Problem constants
// ---------------------------------------------------------------------------
#define BATCH 2
#define SEQ   4096
#define DIM   256
#define NROWS (BATCH * SEQ)        // 8192 rows per view
#define NVIEW 3
#define NVB   (NVIEW * BATCH)      // 6 attention slices
#define IN3   (NVIEW * DIM)        // 768
#define NB    8                    // spline bases per input
#define KCOMB (IN3 + IN3 * NB)     // 6912 = 768 silu cols + 6144 basis cols

// ---------------------------------------------------------------------------
// Device scratch (static allocations only -- no cudaMalloc allowed)
// ---------------------------------------------------------------------------
__device__ float g_q[NVIEW * NROWS * DIM];          // 25 MB
__device__ float g_k[NVIEW * NROWS * DIM];
__device__ float g_v[NVIEW * NROWS * DIM];
__device__ float g_s[(size_t)NVB * SEQ * SEQ];      // 403 MB scores
__device__ float g_att[NVIEW * NROWS * DIM];        // 25 MB
__device__ float g_x[(size_t)NROWS * IN3];          // 25 MB  LN outputs (concat)
__device__ float g_a[(size_t)NROWS * KCOMB];        // 226 MB [silu(x) | bases]
__device__ float g_w[(size_t)DIM * KCOMB];          // 7 MB   [base_w | spline_w*scaler]

// ---------------------------------------------------------------------------
// Generic fp32 GEMM: C[m,n] = sum_k A[m,k] * B'[k,n] (+bias[n])
// BT=true : B is [N,K] row-major (i.e. C = A @ B^T)   -- "NT"
// BT=false: B is [K,N] row-major (i.e. C = A @ B)     -- "NN"
// Tile 128x128x16, 256 threads, 8x8 per thread. All dims are multiples of the
// tile sizes for every call site in this problem (asserted by construction).
// ---------------------------------------------------------------------------
#define BM 128
#define BN 128
#define BK 16
#define TM 8
#define TN 8

template <bool BT>
__global__ __launch_bounds__(256)
void sgemm_kernel(const float* __restrict__ A, const float* __restrict__ B,
                  float* __restrict__ C,
                  int M, int N, int K,
                  long batchStrideA, long batchStrideB, long batchStrideC,
                  const float* __restrict__ bias)
{
    A += (long)blockIdx.z * batchStrideA;
    B += (long)blockIdx.z * batchStrideB;
    C += (long)blockIdx.z * batchStrideC;

    const int bm = blockIdx.y * BM;
    const int bn = blockIdx.x * BN;

    __shared__ float As[BK][BM];
    __shared__ float Bs[BK][BN];

    const int tid = threadIdx.x;
    // A (and NT-B) loader mapping: 128 rows x 16 cols, 2 float4 per thread
    const int a_row  = tid >> 2;        // 0..63  (+64 for second row)
    const int a_col4 = tid & 3;         // which float4 within the 16-wide row
    // NN-B loader mapping: 16 rows x 128 cols
    const int b_row  = tid >> 5;        // 0..7   (+8)
    const int b_col4 = tid & 31;

    const int tm = (tid >> 4) * TM;     // 16x16 thread grid -> 8x8 microtile
    const int tn = (tid & 15) * TN;

    float acc[TM][TN] = {};

    for (int k0 = 0; k0 < K; k0 += BK) {
        // ---- load A tile (transpose into As[k][m]) ----
        #pragma unroll
        for (int r = 0; r < 2; ++r) {
            const int row = a_row + r * 64;
            float4 v = *(const float4*)(A + (long)(bm + row) * K + k0 + a_col4 * 4);
            As[a_col4 * 4 + 0][row] = v.x;
            As[a_col4 * 4 + 1][row] = v.y;
            As[a_col4 * 4 + 2][row] = v.z;
            As[a_col4 * 4 + 3][row] = v.w;
        }
        // ---- load B tile into Bs[k][n] ----
        if (BT) {
            #pragma unroll
            for (int r = 0; r < 2; ++r) {
                const int row = a_row + r * 64;   // output column index
                float4 v = *(const float4*)(B + (long)(bn + row) * K + k0 + a_col4 * 4);
                Bs[a_col4 * 4 + 0][row] = v.x;
                Bs[a_col4 * 4 + 1][row] = v.y;
                Bs[a_col4 * 4 + 2][row] = v.z;
                Bs[a_col4 * 4 + 3][row] = v.w;
            }
        } else {
            #pragma unroll
            for (int r = 0; r < 2; ++r) {
                const int row = b_row + r * 8;    // k index
                float4 v = *(const float4*)(B + (long)(k0 + row) * N + bn + b_col4 * 4);
                *(float4*)&Bs[row][b_col4 * 4] = v;
            }
        }
        __syncthreads();

        #pragma unroll
        for (int kk = 0; kk < BK; ++kk) {
            float4 a0 = *(const float4*)&As[kk][tm];
            float4 a1 = *(const float4*)&As[kk][tm + 4];
            float4 b0 = *(const float4*)&Bs[kk][tn];
            float4 b1 = *(const float4*)&Bs[kk][tn + 4];
            const float av[TM] = {a0.x, a0.y, a0.z, a0.w, a1.x, a1.y, a1.z, a1.w};
            const float bv[TN] = {b0.x, b0.y, b0.z, b0.w, b1.x, b1.y, b1.z, b1.w};
            #pragma unroll
            for (int i = 0; i < TM; ++i)
                #pragma unroll
                for (int j = 0; j < TN; ++j)
                    acc[i][j] += av[i] * bv[j];
        }
        __syncthreads();
    }

    #pragma unroll
    for (int i = 0; i < TM; ++i) {
        const long row = bm + tm + i;
        #pragma unroll
        for (int j = 0; j < TN; ++j) {
            const int col = bn + tn + j;
            float v = acc[i][j];
            if (bias) v += bias[col];
            C[row * N + col] = v;
        }
    }
}

// ---------------------------------------------------------------------------
// Row softmax with score scaling: p = softmax(scale * s) in place.
// (The per-query view-embedding bias of the reference cancels in softmax.)
// ---------------------------------------------------------------------------
__global__ __launch_bounds__(256)
void softmax_kernel(float* __restrict__ S, int ncols, float scale)
{
    float* p = S + (size_t)blockIdx.x * ncols;
    const int tid = threadIdx.x;
    __shared__ float red[8];

    float m = -1e30f;
    for (int c = tid; c < ncols; c += 256) m = fmaxf(m, p[c]);
    #pragma unroll
    for (int o = 16; o; o >>= 1) m = fmaxf(m, __shfl_xor_sync(0xffffffffu, m, o));
    if ((tid & 31) == 0) red[tid >> 5] = m;
    __syncthreads();
    m = red[0];
    #pragma unroll
    for (int i = 1; i < 8; ++i) m = fmaxf(m, red[i]);
    __syncthreads();

    float sum = 0.f;
    for (int c = tid; c < ncols; c += 256) {
        float e = __expf(scale * (p[c] - m));
        p[c] = e;
        sum += e;
    }
    #pragma unroll
    for (int o = 16; o; o >>= 1) sum += __shfl_xor_sync(0xffffffffu, sum, o);
    if ((tid & 31) == 0) red[tid >> 5] = sum;
    __syncthreads();
    sum = 0.f;
    #pragma unroll
    for (int i = 0; i < 8; ++i) sum += red[i];
    const float inv = 1.f / sum;

    for (int c = tid; c < ncols; c += 256) p[c] *= inv;
}

// ---------------------------------------------------------------------------
// y = LayerNorm(att + tokens) * g + b, written into the concatenated x buffer
// One block per row (256 threads = DIM).
// ---------------------------------------------------------------------------
__global__ __launch_bounds__(256)
void resid_ln_kernel(const float* __restrict__ att, const float* __restrict__ tok,
                     const float* __restrict__ g, const float* __restrict__ b,
                     float* __restrict__ xout, int view)
{
    const long row = blockIdx.x;
    const int d = threadIdx.x;
    __shared__ float red[8];

    const float v = att[row * DIM + d] + tok[row * DIM + d];

    float s = v;
    #pragma unroll
    for (int o = 16; o; o >>= 1) s += __shfl_xor_sync(0xffffffffu, s, o);
    if ((d & 31) == 0) red[d >> 5] = s;
    __syncthreads();
    float mean = 0.f;
    #pragma unroll
    for (int i = 0; i < 8; ++i) mean += red[i];
    mean *= (1.f / DIM);
    __syncthreads();

    const float c = v - mean;
    float s2 = c * c;
    #pragma unroll
    for (int o = 16; o; o >>= 1) s2 += __shfl_xor_sync(0xffffffffu, s2, o);
    if ((d & 31) == 0) red[d >> 5] = s2;
    __syncthreads();
    float var = 0.f;
    #pragma unroll
    for (int i = 0; i < 8; ++i) var += red[i];
    var *= (1.f / DIM);

    const float y = c * rsqrtf(var + 1e-5f) * g[d] + b[d];
    xout[row * IN3 + (long)view * DIM + d] = y;
}

// ---------------------------------------------------------------------------
// Build combined weight: W[o, 0:768] = base_weight; W[o, 768 + i*8 + f] =
// spline_weight[o,i,f] * spline_scaler[o,i]
// ---------------------------------------------------------------------------
__global__ __launch_bounds__(256)
void build_w_kernel(const float* __restrict__ bw, const float* __restrict__ sw,
                    const float* __restrict__ sc, float* __restrict__ W)
{
    const long idx = (long)blockIdx.x * blockDim.x + threadIdx.x; // over 256*768
    if (idx >= (long)DIM * IN3) return;
    const int o = (int)(idx / IN3);
    const int i = (int)(idx % IN3);
    W[(long)o * KCOMB + i] = bw[(long)o * IN3 + i];
    const float s = sc[(long)o * IN3 + i];
    const float* swp = sw + ((long)o * IN3 + i) * NB;
    float* wp = W + (long)o * KCOMB + IN3 + (long)i * NB;
    #pragma unroll
    for (int f = 0; f < NB; ++f) wp[f] = swp[f] * s;
}

// ---------------------------------------------------------------------------
// Build A matrix: A[n, 0:768] = silu(x); A[n, 768 + i*8 + f] = bspline_f(x[n,i])
// Cubic B-splines on uniform grid: knots g_j = -1 + (j-3)*0.4, j=0..11.
// ---------------------------------------------------------------------------
__global__ __launch_bounds__(256)
void build_a_kernel(const float* __restrict__ x, float* __restrict__ A)
{
    const long idx = (long)blockIdx.x * blockDim.x + threadIdx.x; // over 8192*768
    if (idx >= (long)NROWS * IN3) return;
    const long n = idx / IN3;
    const int i = (int)(idx % IN3);
    const float v = x[idx];

    // silu
    const float sig = 1.f / (1.f + __expf(-v));
    A[n * KCOMB + i] = v * sig;

    // degree-0 indicators over 11 intervals
    const float h = 0.4f;
    float b[11];
    #pragma unroll
    for (int j = 0; j < 11; ++j) {
        const float gj  = -1.f + (j - 3) * h;
        const float gj1 = -1.f + (j - 2) * h;
        b[j] = (v >= gj && v < gj1) ? 1.f : 0.f;
    }
    // Cox-de Boor recursion up to cubic
    #pragma unroll
    for (int k = 1; k <= 3; ++k) {
        #pragma unroll
        for (int j = 0; j <= 10 - k; ++j) {
            const float gj   = -1.f + (j - 3) * h;
            const float gjk  = -1.f + (j - 3 + k) * h;
            const float gj1  = -1.f + (j - 2) * h;
            const float gjk1 = -1.f + (j - 2 + k) * h;
            b[j] = (v - gj) / (gjk - gj) * b[j] + (gjk1 - v) / (gjk1 - gj1) * b[j + 1];
        }
    }
    float* ap = A + n * KCOMB + IN3 + (long)i * NB;
    #pragma unroll
    for (int f = 0; f < NB; ++f) ap[f] = b[f];
}

// ---------------------------------------------------------------------------
// Host launcher
// ---------------------------------------------------------------------------
extern "C" void kernel_launch(void* const* d_in, const int* in_sizes, int n_in,
                              void* d_out, int out_size)
{
    (void)in_sizes; (void)n_in; (void)out_size;

    const float* tok[NVIEW] = {(const float*)d_in[0], (const float*)d_in[1], (const float*)d_in[2]};
    const float* wq = (const float*)d_in[3];
    const float* bq = (const float*)d_in[4];
    const float* wk = (const float*)d_in[5];
    const float* bk = (const float*)d_in[6];
    const float* wv = (const float*)d_in[7];
    const float* bv = (const float*)d_in[8];
    // d_in[9] = view_emb: per-query constant bias -> softmax-invariant -> unused
    const float* lng[NVIEW] = {(const float*)d_in[10], (const float*)d_in[12], (const float*)d_in[14]};
    const float* lnb[NVIEW] = {(const float*)d_in[11], (const float*)d_in[13], (const float*)d_in[15]};
    const float* bw = (const float*)d_in[16];
    const float* sw = (const float*)d_in[17];
    const float* sc = (const float*)d_in[18];

    float *q, *k, *v, *s, *att, *x, *a, *w;
    cudaGetSymbolAddress((void**)&q,   g_q);
    cudaGetSymbolAddress((void**)&k,   g_k);
    cudaGetSymbolAddress((void**)&v,   g_v);
    cudaGetSymbolAddress((void**)&s,   g_s);
    cudaGetSymbolAddress((void**)&att, g_att);
    cudaGetSymbolAddress((void**)&x,   g_x);
    cudaGetSymbolAddress((void**)&a,   g_a);
    cudaGetSymbolAddress((void**)&w,   g_w);

    const long vStride = (long)NROWS * DIM;      // per-view Q/K/V/att stride
    const long sStride = (long)SEQ * SEQ;        // per-(view,batch) scores stride
    const long qvb     = (long)SEQ * DIM;        // per-(view,batch) qkv stride

    // 1) Q/K/V projections per view: [8192,256] = tok @ W^T + b
    dim3 gProj(DIM / BN, NROWS / BM, 1);
    for (int vi = 0; vi < NVIEW; ++vi) {
        sgemm_kernel<true><<<gProj, 256>>>(tok[vi], wq, q + vi * vStride,
                                           NROWS, DIM, DIM, 0, 0, 0, bq);
        sgemm_kernel<true><<<gProj, 256>>>(tok[vi], wk, k + vi * vStride,
                                           NROWS, DIM, DIM, 0, 0, 0, bk);
        sgemm_kernel<true><<<gProj, 256>>>(tok[vi], wv, v + vi * vStride,
                                           NROWS, DIM, DIM, 0, 0, 0, bv);
    }

    // 2) scores = Q @ K^T for all 6 (view,batch) slices
    dim3 gScore(SEQ / BN, SEQ / BM, NVB);
    sgemm_kernel<true><<<gScore, 256>>>(q, k, s, SEQ, SEQ, DIM,
                                        qvb, qvb, sStride, nullptr);

    // 3) softmax(scale * scores) rows; scale = 1/sqrt(256)
    softmax_kernel<<<NVB * SEQ, 256>>>(s, SEQ, 0.0625f);

    // 4) att = P @ V
    dim3 gAtt(DIM / BN, SEQ / BM, NVB);
    sgemm_kernel<false><<<gAtt, 256>>>(s, v, att, SEQ, DIM, SEQ,
                                       sStride, qvb, qvb, nullptr);

    // 5) LayerNorm(att + tokens) into concatenated x[8192, 768]
    for (int vi = 0; vi < NVIEW; ++vi)
        resid_ln_kernel<<<NROWS, 256>>>(att + vi * vStride, tok[vi],
                                        lng[vi], lnb[vi], x, vi);

    // 6) combined weight and combined A matrix
    build_w_kernel<<<(DIM * IN3 + 255) / 256, 256>>>(bw, sw, sc, w);
    build_a_kernel<<<((long)NROWS * IN3 + 255) / 256, 256>>>(x, a);

    // 7) out = A @ W^T  (fuses base silu-GEMM and spline GEMM, K = 6912)
    dim3 gOut(DIM / BN, NROWS / BM, 1);
    sgemm_kernel<true><<<gOut, 256>>>(a, w, (float*)d_out,
                                      NROWS, DIM, KCOMB, 0, 0, 0, nullptr);
}

// round 5
// speedup vs baseline: 2.2232x; 2.2232x over previous
#include <cuda_runtime.h>
#include <cstdint>

// ---------------------------------------------------------------------------
// Problem constants
// ---------------------------------------------------------------------------
#define BATCH 2
#define SEQ   4096
#define DIM   256
#define NROWS (BATCH * SEQ)        // 8192 rows per view
#define NVIEW 3
#define NVB   (NVIEW * BATCH)      // 6 attention slices
#define IN3   (NVIEW * DIM)        // 768
#define NB    8                    // spline bases per input
#define KCOMB (IN3 + IN3 * NB)     // 6912

// ---------------------------------------------------------------------------
// Device scratch (static allocations only -- no cudaMalloc allowed)
// ---------------------------------------------------------------------------
__device__ float g_q[NVIEW * NROWS * DIM];
__device__ float g_k[NVIEW * NROWS * DIM];
__device__ float g_v[NVIEW * NROWS * DIM];
__device__ float g_s[(size_t)NVB * SEQ * SEQ];      // 403 MB scores
__device__ float g_att[NVIEW * NROWS * DIM];
__device__ float g_x[(size_t)NROWS * IN3];
__device__ float g_a[(size_t)NROWS * KCOMB];        // 226 MB
__device__ float g_w[(size_t)DIM * KCOMB];

// ---------------------------------------------------------------------------
// TF32 helpers
// ---------------------------------------------------------------------------
__device__ __forceinline__ float tf32r(float x) {
    uint32_t u;
    asm("cvt.rna.tf32.f32 %0, %1;" : "=r"(u) : "f"(x));
    return __uint_as_float(u);
}

__device__ __forceinline__ void mma_tf32(float c[4],
                                         uint32_t a0, uint32_t a1, uint32_t a2, uint32_t a3,
                                         uint32_t b0, uint32_t b1) {
    asm("mma.sync.aligned.m16n8k8.row.col.f32.tf32.tf32.f32 "
        "{%0,%1,%2,%3}, {%4,%5,%6,%7}, {%8,%9}, {%0,%1,%2,%3};"
        : "+f"(c[0]), "+f"(c[1]), "+f"(c[2]), "+f"(c[3])
        : "r"(a0), "r"(a1), "r"(a2), "r"(a3), "r"(b0), "r"(b1));
}

// ---------------------------------------------------------------------------
// TF32 tensor-core GEMM: C = A @ op(B) (+bias), fp32 accumulate.
// BT=true : B is [N,K] row-major (C = A @ B^T)
// BT=false: B is [K,N] row-major (C = A @ B)
// Block tile 128x128x32, 256 threads (8 warps as 4Mx2N), warp tile 32x64,
// mma.m16n8k8: per warp 2 m-tiles x 8 n-tiles x 4 k-steps.
// SMEM XOR swizzle -> <=2-way conflicts on fragment loads, vectorized stores.
// All call-site dims are multiples of the tile sizes.
// ---------------------------------------------------------------------------
template <bool BT>
__global__ __launch_bounds__(256)
void tgemm(const float* __restrict__ A, const float* __restrict__ B,
           float* __restrict__ C,
           int M, int N, int K,
           long sA, long sB, long sC,
           const float* __restrict__ bias)
{
    A += (long)blockIdx.z * sA;
    B += (long)blockIdx.z * sB;
    C += (long)blockIdx.z * sC;

    const int bm = blockIdx.y * 128;
    const int bn = blockIdx.x * 128;

    __shared__ float As[128 * 32];   // [m][k], k' = k ^ (8*(m&3))
    __shared__ float Bs[128 * 32];   // BT: [n][k] like As.  NN: [k][n], n' = n ^ (8*(k&3))

    const int tid  = threadIdx.x;
    const int warp = tid >> 5, lane = tid & 31;
    const int wm = warp & 3;          // 0..3 -> 32-row slab
    const int wn = warp >> 2;         // 0..1 -> 64-col slab
    const int g = lane >> 2, t = lane & 3;

    const int r0 = tid >> 3;          // 0..31
    const int c4 = (tid & 7) * 4;     // 0,4,...,28

    float acc[2][8][4];
    #pragma unroll
    for (int i = 0; i < 2; ++i)
        #pragma unroll
        for (int j = 0; j < 8; ++j)
            #pragma unroll
            for (int c = 0; c < 4; ++c) acc[i][j][c] = 0.f;

    for (int k0 = 0; k0 < K; k0 += 32) {
        // ---- A tile: [128 rows][32 k], rows r0+32j, k cols c4..c4+3 ----
        #pragma unroll
        for (int j = 0; j < 4; ++j) {
            const int m = r0 + 32 * j;
            float4 v = *(const float4*)(A + (long)(bm + m) * K + k0 + c4);
            float4 w = {tf32r(v.x), tf32r(v.y), tf32r(v.z), tf32r(v.w)};
            *(float4*)&As[m * 32 + (c4 ^ (8 * (m & 3)))] = w;
        }
        // ---- B tile ----
        if (BT) {
            #pragma unroll
            for (int j = 0; j < 4; ++j) {
                const int n = r0 + 32 * j;
                float4 v = *(const float4*)(B + (long)(bn + n) * K + k0 + c4);
                float4 w = {tf32r(v.x), tf32r(v.y), tf32r(v.z), tf32r(v.w)};
                *(float4*)&Bs[n * 32 + (c4 ^ (8 * (n & 3)))] = w;
            }
        } else {
            #pragma unroll
            for (int j = 0; j < 4; ++j) {
                const int nc = c4 + 32 * j;
                float4 v = *(const float4*)(B + (long)(k0 + r0) * N + bn + nc);
                float4 w = {tf32r(v.x), tf32r(v.y), tf32r(v.z), tf32r(v.w)};
                *(float4*)&Bs[r0 * 128 + (nc ^ (8 * (r0 & 3)))] = w;
            }
        }
        __syncthreads();

        #pragma unroll
        for (int ks = 0; ks < 4; ++ks) {
            const int kk = ks * 8 + t;
            uint32_t a[2][4];
            #pragma unroll
            for (int mt = 0; mt < 2; ++mt) {
                const int m = wm * 32 + mt * 16 + g;   // m&3 == g&3
                const int sw = 8 * (g & 3);
                const float* p = &As[m * 32];
                a[mt][0] = __float_as_uint(p[kk ^ sw]);
                a[mt][1] = __float_as_uint(p[8 * 32 + (kk ^ sw)]);
                a[mt][2] = __float_as_uint(p[(kk + 4) ^ sw]);
                a[mt][3] = __float_as_uint(p[8 * 32 + ((kk + 4) ^ sw)]);
            }
            uint32_t b[8][2];
            #pragma unroll
            for (int nt = 0; nt < 8; ++nt) {
                const int n = wn * 64 + nt * 8 + g;    // n&3 == g&3
                if (BT) {
                    const int sw = 8 * (g & 3);
                    const float* p = &Bs[n * 32];
                    b[nt][0] = __float_as_uint(p[kk ^ sw]);
                    b[nt][1] = __float_as_uint(p[(kk + 4) ^ sw]);
                } else {
                    const int nn = n ^ (8 * t);        // kk&3 == t, (kk+4)&3 == t
                    b[nt][0] = __float_as_uint(Bs[kk * 128 + nn]);
                    b[nt][1] = __float_as_uint(Bs[(kk + 4) * 128 + nn]);
                }
            }
            #pragma unroll
            for (int mt = 0; mt < 2; ++mt)
                #pragma unroll
                for (int nt = 0; nt < 8; ++nt)
                    mma_tf32(acc[mt][nt], a[mt][0], a[mt][1], a[mt][2], a[mt][3],
                             b[nt][0], b[nt][1]);
        }
        __syncthreads();
    }

    // ---- epilogue ----
    #pragma unroll
    for (int mt = 0; mt < 2; ++mt) {
        const int m = bm + wm * 32 + mt * 16 + g;
        #pragma unroll
        for (int nt = 0; nt < 8; ++nt) {
            const int n = bn + wn * 64 + nt * 8 + 2 * t;
            float bx = 0.f, by = 0.f;
            if (bias) { bx = bias[n]; by = bias[n + 1]; }
            float2 v0 = {acc[mt][nt][0] + bx, acc[mt][nt][1] + by};
            float2 v1 = {acc[mt][nt][2] + bx, acc[mt][nt][3] + by};
            *(float2*)(C + (long)m * N + n) = v0;
            *(float2*)(C + (long)(m + 8) * N + n) = v1;
        }
    }
}

// ---------------------------------------------------------------------------
// Row softmax, row cached in registers (one global read + one write).
// Row length fixed at SEQ=4096, 256 threads -> 16 floats (4 float4) each.
// ---------------------------------------------------------------------------
__global__ __launch_bounds__(256)
void softmax_kernel(float* __restrict__ S, float scale)
{
    float4* p = (float4*)(S + (size_t)blockIdx.x * SEQ);
    const int tid = threadIdx.x;
    __shared__ float red[8];

    float4 r[4];
    #pragma unroll
    for (int i = 0; i < 4; ++i) r[i] = p[i * 256 + tid];

    float m = -1e30f;
    #pragma unroll
    for (int i = 0; i < 4; ++i) {
        m = fmaxf(m, fmaxf(fmaxf(r[i].x, r[i].y), fmaxf(r[i].z, r[i].w)));
    }
    #pragma unroll
    for (int o = 16; o; o >>= 1) m = fmaxf(m, __shfl_xor_sync(0xffffffffu, m, o));
    if ((tid & 31) == 0) red[tid >> 5] = m;
    __syncthreads();
    m = red[0];
    #pragma unroll
    for (int i = 1; i < 8; ++i) m = fmaxf(m, red[i]);
    __syncthreads();

    float sum = 0.f;
    #pragma unroll
    for (int i = 0; i < 4; ++i) {
        r[i].x = __expf(scale * (r[i].x - m)); sum += r[i].x;
        r[i].y = __expf(scale * (r[i].y - m)); sum += r[i].y;
        r[i].z = __expf(scale * (r[i].z - m)); sum += r[i].z;
        r[i].w = __expf(scale * (r[i].w - m)); sum += r[i].w;
    }
    #pragma unroll
    for (int o = 16; o; o >>= 1) sum += __shfl_xor_sync(0xffffffffu, sum, o);
    if ((tid & 31) == 0) red[tid >> 5] = sum;
    __syncthreads();
    sum = 0.f;
    #pragma unroll
    for (int i = 0; i < 8; ++i) sum += red[i];
    const float inv = 1.f / sum;

    #pragma unroll
    for (int i = 0; i < 4; ++i) {
        r[i].x *= inv; r[i].y *= inv; r[i].z *= inv; r[i].w *= inv;
        p[i * 256 + tid] = r[i];
    }
}

// ---------------------------------------------------------------------------
// y = LayerNorm(att + tokens) * g + b -> concatenated x buffer
// ---------------------------------------------------------------------------
__global__ __launch_bounds__(256)
void resid_ln_kernel(const float* __restrict__ att, const float* __restrict__ tok,
                     const float* __restrict__ g, const float* __restrict__ b,
                     float* __restrict__ xout, int view)
{
    const long row = blockIdx.x;
    const int d = threadIdx.x;
    __shared__ float red[8];

    const float v = att[row * DIM + d] + tok[row * DIM + d];

    float s = v;
    #pragma unroll
    for (int o = 16; o; o >>= 1) s += __shfl_xor_sync(0xffffffffu, s, o);
    if ((d & 31) == 0) red[d >> 5] = s;
    __syncthreads();
    float mean = 0.f;
    #pragma unroll
    for (int i = 0; i < 8; ++i) mean += red[i];
    mean *= (1.f / DIM);
    __syncthreads();

    const float c = v - mean;
    float s2 = c * c;
    #pragma unroll
    for (int o = 16; o; o >>= 1) s2 += __shfl_xor_sync(0xffffffffu, s2, o);
    if ((d & 31) == 0) red[d >> 5] = s2;
    __syncthreads();
    float var = 0.f;
    #pragma unroll
    for (int i = 0; i < 8; ++i) var += red[i];
    var *= (1.f / DIM);

    const float y = c * rsqrtf(var + 1e-5f) * g[d] + b[d];
    xout[row * IN3 + (long)view * DIM + d] = y;
}

// ---------------------------------------------------------------------------
// Combined weight: [base_w | spline_w * scaler]
// ---------------------------------------------------------------------------
__global__ __launch_bounds__(256)
void build_w_kernel(const float* __restrict__ bw, const float* __restrict__ sw,
                    const float* __restrict__ sc, float* __restrict__ W)
{
    const long idx = (long)blockIdx.x * blockDim.x + threadIdx.x;
    if (idx >= (long)DIM * IN3) return;
    const int o = (int)(idx / IN3);
    const int i = (int)(idx % IN3);
    W[(long)o * KCOMB + i] = bw[(long)o * IN3 + i];
    const float s = sc[(long)o * IN3 + i];
    const float* swp = sw + ((long)o * IN3 + i) * NB;
    float* wp = W + (long)o * KCOMB + IN3 + (long)i * NB;
    #pragma unroll
    for (int f = 0; f < NB; ++f) wp[f] = swp[f] * s;
}

// ---------------------------------------------------------------------------
// Combined A matrix: [silu(x) | cubic b-spline bases of x]
// ---------------------------------------------------------------------------
__global__ __launch_bounds__(256)
void build_a_kernel(const float* __restrict__ x, float* __restrict__ A)
{
    const long idx = (long)blockIdx.x * blockDim.x + threadIdx.x;
    if (idx >= (long)NROWS * IN3) return;
    const long n = idx / IN3;
    const int i = (int)(idx % IN3);
    const float v = x[idx];

    const float sig = 1.f / (1.f + __expf(-v));
    A[n * KCOMB + i] = v * sig;

    const float h = 0.4f;
    float b[11];
    #pragma unroll
    for (int j = 0; j < 11; ++j) {
        const float gj  = -1.f + (j - 3) * h;
        const float gj1 = -1.f + (j - 2) * h;
        b[j] = (v >= gj && v < gj1) ? 1.f : 0.f;
    }
    #pragma unroll
    for (int k = 1; k <= 3; ++k) {
        #pragma unroll
        for (int j = 0; j <= 10 - k; ++j) {
            const float gj   = -1.f + (j - 3) * h;
            const float gjk  = -1.f + (j - 3 + k) * h;
            const float gj1  = -1.f + (j - 2) * h;
            const float gjk1 = -1.f + (j - 2 + k) * h;
            b[j] = (v - gj) / (gjk - gj) * b[j] + (gjk1 - v) / (gjk1 - gj1) * b[j + 1];
        }
    }
    float* ap = A + n * KCOMB + IN3 + (long)i * NB;
    #pragma unroll
    for (int f = 0; f < NB; ++f) ap[f] = b[f];
}

// ---------------------------------------------------------------------------
// Host launcher
// ---------------------------------------------------------------------------
extern "C" void kernel_launch(void* const* d_in, const int* in_sizes, int n_in,
                              void* d_out, int out_size)
{
    (void)in_sizes; (void)n_in; (void)out_size;

    const float* tok[NVIEW] = {(const float*)d_in[0], (const float*)d_in[1], (const float*)d_in[2]};
    const float* wq = (const float*)d_in[3];
    const float* bq = (const float*)d_in[4];
    const float* wk = (const float*)d_in[5];
    const float* bk = (const float*)d_in[6];
    const float* wv = (const float*)d_in[7];
    const float* bv = (const float*)d_in[8];
    // d_in[9] = view_emb: per-query constant bias -> softmax-invariant -> unused
    const float* lng[NVIEW] = {(const float*)d_in[10], (const float*)d_in[12], (const float*)d_in[14]};
    const float* lnb[NVIEW] = {(const float*)d_in[11], (const float*)d_in[13], (const float*)d_in[15]};
    const float* bw = (const float*)d_in[16];
    const float* sw = (const float*)d_in[17];
    const float* sc = (const float*)d_in[18];

    float *q, *k, *v, *s, *att, *x, *a, *w;
    cudaGetSymbolAddress((void**)&q,   g_q);
    cudaGetSymbolAddress((void**)&k,   g_k);
    cudaGetSymbolAddress((void**)&v,   g_v);
    cudaGetSymbolAddress((void**)&s,   g_s);
    cudaGetSymbolAddress((void**)&att, g_att);
    cudaGetSymbolAddress((void**)&x,   g_x);
    cudaGetSymbolAddress((void**)&a,   g_a);
    cudaGetSymbolAddress((void**)&w,   g_w);

    const long vStride = (long)NROWS * DIM;
    const long sStride = (long)SEQ * SEQ;
    const long qvb     = (long)SEQ * DIM;

    // 1) Q/K/V projections per view
    dim3 gProj(DIM / 128, NROWS / 128, 1);
    for (int vi = 0; vi < NVIEW; ++vi) {
        tgemm<true><<<gProj, 256>>>(tok[vi], wq, q + vi * vStride, NROWS, DIM, DIM, 0, 0, 0, bq);
        tgemm<true><<<gProj, 256>>>(tok[vi], wk, k + vi * vStride, NROWS, DIM, DIM, 0, 0, 0, bk);
        tgemm<true><<<gProj, 256>>>(tok[vi], wv, v + vi * vStride, NROWS, DIM, DIM, 0, 0, 0, bv);
    }

    // 2) scores = Q @ K^T, all 6 (view,batch) slices
    dim3 gScore(SEQ / 128, SEQ / 128, NVB);
    tgemm<true><<<gScore, 256>>>(q, k, s, SEQ, SEQ, DIM, qvb, qvb, sStride, nullptr);

    // 3) softmax(scores / 16) rows
    softmax_kernel<<<NVB * SEQ, 256>>>(s, 0.0625f);

    // 4) att = P @ V
    dim3 gAtt(DIM / 128, SEQ / 128, NVB);
    tgemm<false><<<gAtt, 256>>>(s, v, att, SEQ, DIM, SEQ, sStride, qvb, qvb, nullptr);

    // 5) LayerNorm(att + tokens) -> concat x
    for (int vi = 0; vi < NVIEW; ++vi)
        resid_ln_kernel<<<NROWS, 256>>>(att + vi * vStride, tok[vi], lng[vi], lnb[vi], x, vi);

    // 6) combined weight / combined A
    build_w_kernel<<<(DIM * IN3 + 255) / 256, 256>>>(bw, sw, sc, w);
    build_a_kernel<<<(int)(((long)NROWS * IN3 + 255) / 256), 256>>>(x, a);

    // 7) out = A @ W^T (base + spline fused, K = 6912)
    dim3 gOut(DIM / 128, NROWS / 128, 1);
    tgemm<true><<<gOut, 256>>>(a, w, (float*)d_out, NROWS, DIM, KCOMB, 0, 0, 0, nullptr);
}

// round 6
// speedup vs baseline: 3.2988x; 1.4838x over previous
#include <cuda_runtime.h>
#include <cstdint>

// ---------------------------------------------------------------------------
// Problem constants
// ---------------------------------------------------------------------------
#define BATCH 2
#define SEQ   4096
#define DIM   256
#define NROWS (BATCH * SEQ)        // 8192 rows per view
#define NVIEW 3
#define NVB   (NVIEW * BATCH)      // 6 attention slices
#define IN3   (NVIEW * DIM)        // 768
#define NB    8
#define KCOMB (IN3 + IN3 * NB)     // 6912
#define QKVN  (3 * DIM)            // 768 packed q|k|v columns

// ---------------------------------------------------------------------------
// Device scratch (static only -- no cudaMalloc allowed)
// ---------------------------------------------------------------------------
__device__ float g_tok [(size_t)NVIEW * NROWS * DIM];      // tf32-rounded tokens
__device__ float g_wqkv[(size_t)QKVN * DIM];               // [768,256] packed W
__device__ float g_bqkv[QKVN];
__device__ float g_qkv [(size_t)NVIEW * NROWS * QKVN];     // 75 MB  [row][q|k|v]
__device__ float g_s   [(size_t)NVB * SEQ * SEQ];          // 403 MB scores/probs
__device__ float g_att [(size_t)NVIEW * NROWS * DIM];
__device__ float g_x   [(size_t)NROWS * IN3];
__device__ float g_a   [(size_t)NROWS * KCOMB];            // 226 MB
__device__ float g_w   [(size_t)DIM * KCOMB];

// ---------------------------------------------------------------------------
// TF32 / async helpers
// ---------------------------------------------------------------------------
__device__ __forceinline__ float tf32r(float x) {
    uint32_t u;
    asm("cvt.rna.tf32.f32 %0, %1;" : "=r"(u) : "f"(x));
    return __uint_as_float(u);
}

__device__ __forceinline__ void cp16(void* smem_dst, const void* gsrc) {
    uint32_t d = (uint32_t)__cvta_generic_to_shared(smem_dst);
    asm volatile("cp.async.cg.shared.global [%0], [%1], 16;" :: "r"(d), "l"(gsrc));
}
__device__ __forceinline__ void cp_commit() { asm volatile("cp.async.commit_group;"); }
template <int N>
__device__ __forceinline__ void cp_wait() { asm volatile("cp.async.wait_group %0;" :: "n"(N)); }

__device__ __forceinline__ void mma_tf32(float c[4],
                                         uint32_t a0, uint32_t a1, uint32_t a2, uint32_t a3,
                                         uint32_t b0, uint32_t b1) {
    asm("mma.sync.aligned.m16n8k8.row.col.f32.tf32.tf32.f32 "
        "{%0,%1,%2,%3}, {%4,%5,%6,%7}, {%8,%9}, {%0,%1,%2,%3};"
        : "+f"(c[0]), "+f"(c[1]), "+f"(c[2]), "+f"(c[3])
        : "r"(a0), "r"(a1), "r"(a2), "r"(a3), "r"(b0), "r"(b1));
}

// ---------------------------------------------------------------------------
// TF32 tensor-core GEMM, 3-stage cp.async pipeline.
// C = A @ op(B) (+bias), fp32 accumulate. Inputs must already be TF32-rounded.
// BT=true : B is [N,K] row-major (leading dim ldb)   C = A @ B^T
// BT=false: B is [K,N] row-major (leading dim ldb)   C = A @ B
// Block tile 128x128x32, 256 threads (8 warps 4Mx2N), warp tile 32x64.
// Dynamic smem: 3 stages x (As 16KB + Bs 16KB) = 96KB -> 2 CTAs/SM.
// All call-site dims are multiples of the tile sizes.
// ---------------------------------------------------------------------------
#define STAGES 3
#define STG_F  (128 * 32)          // floats per stage per operand

template <bool BT>
__global__ __launch_bounds__(256, 2)
void tgemm(const float* __restrict__ A, int lda,
           const float* __restrict__ B, int ldb,
           float* __restrict__ C, int ldc,
           int K, long sA, long sB, long sC,
           const float* __restrict__ bias, int roundOut)
{
    A += (long)blockIdx.z * sA;
    B += (long)blockIdx.z * sB;
    C += (long)blockIdx.z * sC;

    extern __shared__ float sm[];
    float* Asm = sm;                     // STAGES * STG_F
    float* Bsm = sm + STAGES * STG_F;    // STAGES * STG_F

    const int bm = blockIdx.y * 128;
    const int bn = blockIdx.x * 128;

    const int tid  = threadIdx.x;
    const int warp = tid >> 5, lane = tid & 31;
    const int wm = warp & 3;
    const int wn = warp >> 2;
    const int g = lane >> 2, t = lane & 3;

    const int r0 = tid >> 3;             // 0..31
    const int c4 = (tid & 7) * 4;        // 0,4,...,28

    float acc[2][8][4];
    #pragma unroll
    for (int i = 0; i < 2; ++i)
        #pragma unroll
        for (int j = 0; j < 8; ++j)
            #pragma unroll
            for (int c = 0; c < 4; ++c) acc[i][j][c] = 0.f;

    const int niter = K >> 5;

    // ---- stage fetch: A tile [128m x 32k], B tile per variant ----
    auto fetch = [&](int stage, int k0) {
        float* as = Asm + stage * STG_F;
        float* bs = Bsm + stage * STG_F;
        #pragma unroll
        for (int j = 0; j < 4; ++j) {
            const int m = r0 + 32 * j;
            cp16(&as[m * 32 + (c4 ^ (8 * (m & 3)))],
                 A + (long)(bm + m) * lda + k0 + c4);
        }
        if (BT) {
            #pragma unroll
            for (int j = 0; j < 4; ++j) {
                const int n = r0 + 32 * j;
                cp16(&bs[n * 32 + (c4 ^ (8 * (n & 3)))],
                     B + (long)(bn + n) * ldb + k0 + c4);
            }
        } else {
            #pragma unroll
            for (int j = 0; j < 4; ++j) {
                const int nc = c4 + 32 * j;
                cp16(&bs[r0 * 128 + (nc ^ (8 * (r0 & 3)))],
                     B + (long)(k0 + r0) * ldb + bn + nc);
            }
        }
    };

    // prologue: fill STAGES-1 stages
    #pragma unroll
    for (int s = 0; s < STAGES - 1; ++s) {
        if (s < niter) fetch(s, s * 32);
        cp_commit();
    }

    for (int i = 0; i < niter; ++i) {
        cp_wait<STAGES - 2>();
        __syncthreads();

        const int pf = i + STAGES - 1;
        if (pf < niter) fetch(pf % STAGES, pf * 32);
        cp_commit();

        const float* as = Asm + (i % STAGES) * STG_F;
        const float* bs = Bsm + (i % STAGES) * STG_F;

        #pragma unroll
        for (int ks = 0; ks < 4; ++ks) {
            const int kk = ks * 8 + t;
            uint32_t a[2][4];
            #pragma unroll
            for (int mt = 0; mt < 2; ++mt) {
                const int m = wm * 32 + mt * 16 + g;
                const int sw = 8 * (g & 3);
                const float* p = &as[m * 32];
                a[mt][0] = __float_as_uint(p[kk ^ sw]);
                a[mt][1] = __float_as_uint(p[8 * 32 + (kk ^ sw)]);
                a[mt][2] = __float_as_uint(p[(kk + 4) ^ sw]);
                a[mt][3] = __float_as_uint(p[8 * 32 + ((kk + 4) ^ sw)]);
            }
            uint32_t b[8][2];
            #pragma unroll
            for (int nt = 0; nt < 8; ++nt) {
                const int n = wn * 64 + nt * 8 + g;
                if (BT) {
                    const int sw = 8 * (g & 3);
                    const float* p = &bs[n * 32];
                    b[nt][0] = __float_as_uint(p[kk ^ sw]);
                    b[nt][1] = __float_as_uint(p[(kk + 4) ^ sw]);
                } else {
                    const int nn = n ^ (8 * t);
                    b[nt][0] = __float_as_uint(bs[kk * 128 + nn]);
                    b[nt][1] = __float_as_uint(bs[(kk + 4) * 128 + nn]);
                }
            }
            #pragma unroll
            for (int mt = 0; mt < 2; ++mt)
                #pragma unroll
                for (int nt = 0; nt < 8; ++nt)
                    mma_tf32(acc[mt][nt], a[mt][0], a[mt][1], a[mt][2], a[mt][3],
                             b[nt][0], b[nt][1]);
        }
        __syncthreads();
    }

    // ---- epilogue ----
    #pragma unroll
    for (int mt = 0; mt < 2; ++mt) {
        const int m = bm + wm * 32 + mt * 16 + g;
        #pragma unroll
        for (int nt = 0; nt < 8; ++nt) {
            const int n = bn + wn * 64 + nt * 8 + 2 * t;
            float bx = 0.f, by = 0.f;
            if (bias) { bx = bias[n]; by = bias[n + 1]; }
            float v0x = acc[mt][nt][0] + bx, v0y = acc[mt][nt][1] + by;
            float v1x = acc[mt][nt][2] + bx, v1y = acc[mt][nt][3] + by;
            if (roundOut) {
                v0x = tf32r(v0x); v0y = tf32r(v0y);
                v1x = tf32r(v1x); v1y = tf32r(v1y);
            }
            *(float2*)(C + (long)m * ldc + n) = make_float2(v0x, v0y);
            *(float2*)(C + (long)(m + 8) * ldc + n) = make_float2(v1x, v1y);
        }
    }
}

// ---------------------------------------------------------------------------
// Round-copy tokens to TF32 scratch
// ---------------------------------------------------------------------------
__global__ __launch_bounds__(256)
void round_copy(const float* __restrict__ src, float* __restrict__ dst, int n)
{
    const int i = blockIdx.x * 1024 + threadIdx.x * 4;
    if (i >= n) return;
    float4 v = *(const float4*)(src + i);
    v.x = tf32r(v.x); v.y = tf32r(v.y); v.z = tf32r(v.z); v.w = tf32r(v.w);
    *(float4*)(dst + i) = v;
}

// ---------------------------------------------------------------------------
// Pack [wq;wk;wv] -> g_wqkv (tf32) and [bq;bk;bv] -> g_bqkv
// ---------------------------------------------------------------------------
__global__ __launch_bounds__(256)
void build_wqkv(const float* __restrict__ wq, const float* __restrict__ wk,
                const float* __restrict__ wv, const float* __restrict__ bq,
                const float* __restrict__ bk, const float* __restrict__ bv,
                float* __restrict__ W, float* __restrict__ Bb)
{
    const int idx = blockIdx.x * 256 + threadIdx.x;
    if (idx >= QKVN * DIM) return;
    const int r = idx / DIM, c = idx % DIM;
    const float* w = (r < DIM) ? wq : (r < 2 * DIM) ? wk : wv;
    W[idx] = tf32r(w[(r & (DIM - 1)) * DIM + c]);
    if (idx < QKVN) {
        const float* b = (idx < DIM) ? bq : (idx < 2 * DIM) ? bk : bv;
        Bb[idx] = b[idx & (DIM - 1)];
    }
}

// ---------------------------------------------------------------------------
// Row softmax, register-cached row; writes TF32-rounded probabilities.
// ---------------------------------------------------------------------------
__global__ __launch_bounds__(256)
void softmax_kernel(float* __restrict__ S, float scale)
{
    float4* p = (float4*)(S + (size_t)blockIdx.x * SEQ);
    const int tid = threadIdx.x;
    __shared__ float red[8];

    float4 r[4];
    #pragma unroll
    for (int i = 0; i < 4; ++i) r[i] = p[i * 256 + tid];

    float m = -1e30f;
    #pragma unroll
    for (int i = 0; i < 4; ++i)
        m = fmaxf(m, fmaxf(fmaxf(r[i].x, r[i].y), fmaxf(r[i].z, r[i].w)));
    #pragma unroll
    for (int o = 16; o; o >>= 1) m = fmaxf(m, __shfl_xor_sync(0xffffffffu, m, o));
    if ((tid & 31) == 0) red[tid >> 5] = m;
    __syncthreads();
    m = red[0];
    #pragma unroll
    for (int i = 1; i < 8; ++i) m = fmaxf(m, red[i]);
    __syncthreads();

    float sum = 0.f;
    #pragma unroll
    for (int i = 0; i < 4; ++i) {
        r[i].x = __expf(scale * (r[i].x - m)); sum += r[i].x;
        r[i].y = __expf(scale * (r[i].y - m)); sum += r[i].y;
        r[i].z = __expf(scale * (r[i].z - m)); sum += r[i].z;
        r[i].w = __expf(scale * (r[i].w - m)); sum += r[i].w;
    }
    #pragma unroll
    for (int o = 16; o; o >>= 1) sum += __shfl_xor_sync(0xffffffffu, sum, o);
    if ((tid & 31) == 0) red[tid >> 5] = sum;
    __syncthreads();
    sum = 0.f;
    #pragma unroll
    for (int i = 0; i < 8; ++i) sum += red[i];
    const float inv = 1.f / sum;

    #pragma unroll
    for (int i = 0; i < 4; ++i) {
        r[i].x = tf32r(r[i].x * inv); r[i].y = tf32r(r[i].y * inv);
        r[i].z = tf32r(r[i].z * inv); r[i].w = tf32r(r[i].w * inv);
        p[i * 256 + tid] = r[i];
    }
}

// ---------------------------------------------------------------------------
// y = LayerNorm(att + tokens) * g + b -> concatenated x buffer
// ---------------------------------------------------------------------------
__global__ __launch_bounds__(256)
void resid_ln_kernel(const float* __restrict__ att, const float* __restrict__ tok,
                     const float* __restrict__ g, const float* __restrict__ b,
                     float* __restrict__ xout, int view)
{
    const long row = blockIdx.x;
    const int d = threadIdx.x;
    __shared__ float red[8];

    const float v = att[row * DIM + d] + tok[row * DIM + d];

    float s = v;
    #pragma unroll
    for (int o = 16; o; o >>= 1) s += __shfl_xor_sync(0xffffffffu, s, o);
    if ((d & 31) == 0) red[d >> 5] = s;
    __syncthreads();
    float mean = 0.f;
    #pragma unroll
    for (int i = 0; i < 8; ++i) mean += red[i];
    mean *= (1.f / DIM);
    __syncthreads();

    const float c = v - mean;
    float s2 = c * c;
    #pragma unroll
    for (int o = 16; o; o >>= 1) s2 += __shfl_xor_sync(0xffffffffu, s2, o);
    if ((d & 31) == 0) red[d >> 5] = s2;
    __syncthreads();
    float var = 0.f;
    #pragma unroll
    for (int i = 0; i < 8; ++i) var += red[i];
    var *= (1.f / DIM);

    const float y = c * rsqrtf(var + 1e-5f) * g[d] + b[d];
    xout[row * IN3 + (long)view * DIM + d] = y;
}

// ---------------------------------------------------------------------------
// Combined weight: [base_w | spline_w * scaler], TF32-rounded
// ---------------------------------------------------------------------------
__global__ __launch_bounds__(256)
void build_w_kernel(const float* __restrict__ bw, const float* __restrict__ sw,
                    const float* __restrict__ sc, float* __restrict__ W)
{
    const long idx = (long)blockIdx.x * blockDim.x + threadIdx.x;
    if (idx >= (long)DIM * IN3) return;
    const int o = (int)(idx / IN3);
    const int i = (int)(idx % IN3);
    W[(long)o * KCOMB + i] = tf32r(bw[(long)o * IN3 + i]);
    const float s = sc[(long)o * IN3 + i];
    const float* swp = sw + ((long)o * IN3 + i) * NB;
    float* wp = W + (long)o * KCOMB + IN3 + (long)i * NB;
    #pragma unroll
    for (int f = 0; f < NB; ++f) wp[f] = tf32r(swp[f] * s);
}

// ---------------------------------------------------------------------------
// Combined A: [silu(x) | cubic b-spline bases], TF32-rounded
// ---------------------------------------------------------------------------
__global__ __launch_bounds__(256)
void build_a_kernel(const float* __restrict__ x, float* __restrict__ A)
{
    const long idx = (long)blockIdx.x * blockDim.x + threadIdx.x;
    if (idx >= (long)NROWS * IN3) return;
    const long n = idx / IN3;
    const int i = (int)(idx % IN3);
    const float v = x[idx];

    const float sig = 1.f / (1.f + __expf(-v));
    A[n * KCOMB + i] = tf32r(v * sig);

    const float h = 0.4f;
    float b[11];
    #pragma unroll
    for (int j = 0; j < 11; ++j) {
        const float gj  = -1.f + (j - 3) * h;
        const float gj1 = -1.f + (j - 2) * h;
        b[j] = (v >= gj && v < gj1) ? 1.f : 0.f;
    }
    #pragma unroll
    for (int k = 1; k <= 3; ++k) {
        #pragma unroll
        for (int j = 0; j <= 10 - k; ++j) {
            const float gj   = -1.f + (j - 3) * h;
            const float gjk  = -1.f + (j - 3 + k) * h;
            const float gj1  = -1.f + (j - 2) * h;
            const float gjk1 = -1.f + (j - 2 + k) * h;
            b[j] = (v - gj) / (gjk - gj) * b[j] + (gjk1 - v) / (gjk1 - gj1) * b[j + 1];
        }
    }
    float* ap = A + n * KCOMB + IN3 + (long)i * NB;
    #pragma unroll
    for (int f = 0; f < NB; ++f) ap[f] = tf32r(b[f]);
}

// ---------------------------------------------------------------------------
// Host launcher
// ---------------------------------------------------------------------------
extern "C" void kernel_launch(void* const* d_in, const int* in_sizes, int n_in,
                              void* d_out, int out_size)
{
    (void)in_sizes; (void)n_in; (void)out_size;

    const float* tok[NVIEW] = {(const float*)d_in[0], (const float*)d_in[1], (const float*)d_in[2]};
    const float* wq = (const float*)d_in[3];
    const float* bq = (const float*)d_in[4];
    const float* wk = (const float*)d_in[5];
    const float* bk = (const float*)d_in[6];
    const float* wv = (const float*)d_in[7];
    const float* bv = (const float*)d_in[8];
    // d_in[9] = view_emb: per-query constant bias -> softmax-invariant -> unused
    const float* lng[NVIEW] = {(const float*)d_in[10], (const float*)d_in[12], (const float*)d_in[14]};
    const float* lnb[NVIEW] = {(const float*)d_in[11], (const float*)d_in[13], (const float*)d_in[15]};
    const float* bw = (const float*)d_in[16];
    const float* sw = (const float*)d_in[17];
    const float* sc = (const float*)d_in[18];

    float *ptok, *pwqkv, *pbqkv, *pqkv, *s, *att, *x, *a, *w;
    cudaGetSymbolAddress((void**)&ptok,  g_tok);
    cudaGetSymbolAddress((void**)&pwqkv, g_wqkv);
    cudaGetSymbolAddress((void**)&pbqkv, g_bqkv);
    cudaGetSymbolAddress((void**)&pqkv,  g_qkv);
    cudaGetSymbolAddress((void**)&s,     g_s);
    cudaGetSymbolAddress((void**)&att,   g_att);
    cudaGetSymbolAddress((void**)&x,     g_x);
    cudaGetSymbolAddress((void**)&a,     g_a);
    cudaGetSymbolAddress((void**)&w,     g_w);

    static int smemSet = 0;
    const int SMEM = STAGES * STG_F * 2 * (int)sizeof(float);   // 96 KB
    if (!smemSet) {
        cudaFuncSetAttribute(tgemm<true>,  cudaFuncAttributeMaxDynamicSharedMemorySize, SMEM);
        cudaFuncSetAttribute(tgemm<false>, cudaFuncAttributeMaxDynamicSharedMemorySize, SMEM);
        smemSet = 1;
    }

    const long vStride  = (long)NROWS * DIM;        // per-view att stride
    const long qkvSlice = (long)SEQ * QKVN;         // per-(view,batch) qkv rows
    const long sStride  = (long)SEQ * SEQ;

    // 0) pack tokens (tf32) and qkv weights
    const int ntok = NROWS * DIM;
    for (int vi = 0; vi < NVIEW; ++vi)
        round_copy<<<(ntok + 1023) / 1024, 256>>>(tok[vi], ptok + (long)vi * ntok, ntok);
    build_wqkv<<<(QKVN * DIM + 255) / 256, 256>>>(wq, wk, wv, bq, bk, bv, pwqkv, pbqkv);

    // 1) fused QKV: [24576,768] = tok @ Wqkv^T + bqkv (outputs tf32-rounded)
    {
        dim3 grid(QKVN / 128, (NVIEW * NROWS) / 128, 1);
        tgemm<true><<<grid, 256, SMEM>>>(ptok, DIM, pwqkv, DIM, pqkv, QKVN,
                                         DIM, 0, 0, 0, pbqkv, 1);
    }

    // 2) scores = Q @ K^T for all 6 (view,batch) slices
    {
        dim3 grid(SEQ / 128, SEQ / 128, NVB);
        tgemm<true><<<grid, 256, SMEM>>>(pqkv + 0, QKVN, pqkv + DIM, QKVN, s, SEQ,
                                         DIM, qkvSlice, qkvSlice, sStride, nullptr, 0);
    }

    // 3) softmax(scores / 16), writes tf32 probs
    softmax_kernel<<<NVB * SEQ, 256>>>(s, 0.0625f);

    // 4) att = P @ V
    {
        dim3 grid(DIM / 128, SEQ / 128, NVB);
        tgemm<false><<<grid, 256, SMEM>>>(s, SEQ, pqkv + 2 * DIM, QKVN, att, DIM,
                                          SEQ, sStride, qkvSlice, (long)SEQ * DIM, nullptr, 0);
    }

    // 5) LayerNorm(att + tokens) -> concat x
    for (int vi = 0; vi < NVIEW; ++vi)
        resid_ln_kernel<<<NROWS, 256>>>(att + vi * vStride, tok[vi], lng[vi], lnb[vi], x, vi);

    // 6) combined weight / combined A (both tf32-rounded)
    build_w_kernel<<<(DIM * IN3 + 255) / 256, 256>>>(bw, sw, sc, w);
    build_a_kernel<<<(int)(((long)NROWS * IN3 + 255) / 256), 256>>>(x, a);

    // 7) out = A @ W^T (base + spline fused, K = 6912)
    {
        dim3 grid(DIM / 128, NROWS / 128, 1);
        tgemm<true><<<grid, 256, SMEM>>>(a, KCOMB, w, KCOMB, (float*)d_out, DIM,
                                         KCOMB, 0, 0, 0, nullptr, 0);
    }
}

// round 7
// speedup vs baseline: 4.8612x; 1.4736x over previous
#include <cuda_runtime.h>
#include <cuda_fp16.h>
#include <cstdint>

// ---------------------------------------------------------------------------
// Problem constants
// ---------------------------------------------------------------------------
#define BATCH 2
#define SEQ   4096
#define DIM   256
#define NROWS (BATCH * SEQ)        // 8192 rows per view
#define NVIEW 3
#define NVB   (NVIEW * BATCH)      // 6 attention slices
#define IN3   (NVIEW * DIM)        // 768
#define NB    8
#define KCOMB (IN3 + IN3 * NB)     // 6912
#define QKVN  (3 * DIM)            // 768 packed q|k|v columns
#define ROWS3 (NVIEW * NROWS)      // 24576

// ---------------------------------------------------------------------------
// Device scratch (static only -- no cudaMalloc allowed)
// ---------------------------------------------------------------------------
__device__ __half g_tok [(size_t)ROWS3 * DIM];        // fp16 tokens (concat views)
__device__ __half g_wqkv[(size_t)QKVN * DIM];         // packed [wq;wk;wv] fp16
__device__ float  g_bqkv[QKVN];
__device__ __half g_qkv [(size_t)ROWS3 * QKVN];       // 37.7 MB [row][q|k|v]
__device__ __half g_vt  [(size_t)NVB * DIM * SEQ];    // 12.5 MB V^T per slice
__device__ float  g_s   [(size_t)NVB * SEQ * SEQ];    // 403 MB fp32 scores
__device__ __half g_p   [(size_t)NVB * SEQ * SEQ];    // 202 MB fp16 probs
__device__ float  g_att [(size_t)ROWS3 * DIM];
__device__ float  g_x   [(size_t)NROWS * IN3];
__device__ __half g_a   [(size_t)NROWS * KCOMB];      // 113 MB
__device__ __half g_w   [(size_t)DIM * KCOMB];

// ---------------------------------------------------------------------------
// Async / mma helpers
// ---------------------------------------------------------------------------
__device__ __forceinline__ void cp16(void* smem_dst, const void* gsrc) {
    uint32_t d = (uint32_t)__cvta_generic_to_shared(smem_dst);
    asm volatile("cp.async.cg.shared.global [%0], [%1], 16;" :: "r"(d), "l"(gsrc));
}
__device__ __forceinline__ void cp_commit() { asm volatile("cp.async.commit_group;"); }
template <int N>
__device__ __forceinline__ void cp_wait() { asm volatile("cp.async.wait_group %0;" :: "n"(N)); }

__device__ __forceinline__ void mma_f16(float c[4],
                                        uint32_t a0, uint32_t a1, uint32_t a2, uint32_t a3,
                                        uint32_t b0, uint32_t b1) {
    asm("mma.sync.aligned.m16n8k16.row.col.f32.f16.f16.f32 "
        "{%0,%1,%2,%3}, {%4,%5,%6,%7}, {%8,%9}, {%0,%1,%2,%3};"
        : "+f"(c[0]), "+f"(c[1]), "+f"(c[2]), "+f"(c[3])
        : "r"(a0), "r"(a1), "r"(a2), "r"(a3), "r"(b0), "r"(b1));
}

// ---------------------------------------------------------------------------
// FP16 tensor-core GEMM (NT only): C = A @ B^T (+bias), fp32 accumulate.
// A [M,K] fp16 (ld lda), B [N,K] fp16 (ld ldb), C fp32 or fp16 per OUTH.
// Block tile 128x128x32, 256 threads (8 warps 4Mx2N), warp tile 32x64,
// mma m16n8k16, 3-stage cp.async pipeline, pad-40 SMEM rows (conflict-free).
// 61.4 KB dynamic smem -> 2 CTAs/SM. All call-site dims tile-multiple.
// ---------------------------------------------------------------------------
#define STAGES 3
#define AROW   40                  // halfs per smem row (32 data + 8 pad)
#define STG_H  (128 * AROW)        // halfs per stage per operand

template <bool OUTH>
__global__ __launch_bounds__(256, 2)
void hgemm(const __half* __restrict__ A, int lda,
           const __half* __restrict__ B, int ldb,
           void* __restrict__ Cv, int ldc, int K,
           long sA, long sB, long sC,
           const float* __restrict__ bias)
{
    A += (long)blockIdx.z * sA;
    B += (long)blockIdx.z * sB;

    extern __shared__ __half sm[];
    __half* Asm = sm;
    __half* Bsm = sm + STAGES * STG_H;

    const int bm = blockIdx.y * 128;
    const int bn = blockIdx.x * 128;

    const int tid  = threadIdx.x;
    const int warp = tid >> 5, lane = tid & 31;
    const int wm = warp & 3;
    const int wn = warp >> 2;
    const int g = lane >> 2, t = lane & 3;

    const int r0 = tid >> 2;           // 0..63
    const int q8 = (tid & 3) * 8;      // half offset within 32-wide k row

    float acc[2][8][4] = {};

    const int niter = K >> 5;

    auto fetch = [&](int stage, int k0) {
        __half* as = Asm + stage * STG_H;
        __half* bs = Bsm + stage * STG_H;
        #pragma unroll
        for (int j = 0; j < 2; ++j) {
            const int r = r0 + 64 * j;
            cp16(&as[r * AROW + q8], A + (long)(bm + r) * lda + k0 + q8);
            cp16(&bs[r * AROW + q8], B + (long)(bn + r) * ldb + k0 + q8);
        }
    };

    #pragma unroll
    for (int s = 0; s < STAGES - 1; ++s) {
        if (s < niter) fetch(s, s * 32);
        cp_commit();
    }

    for (int i = 0; i < niter; ++i) {
        cp_wait<STAGES - 2>();
        __syncthreads();

        const int pf = i + STAGES - 1;
        if (pf < niter) fetch(pf % STAGES, pf * 32);
        cp_commit();

        const __half* as = Asm + (i % STAGES) * STG_H;
        const __half* bs = Bsm + (i % STAGES) * STG_H;

        #pragma unroll
        for (int ks = 0; ks < 2; ++ks) {
            const int kk = ks * 16 + 2 * t;   // this thread's first k (half idx)
            uint32_t a[2][4];
            #pragma unroll
            for (int mt = 0; mt < 2; ++mt) {
                const int m = wm * 32 + mt * 16 + g;
                const uint32_t* p0 = (const uint32_t*)&as[m * AROW + kk];
                const uint32_t* p1 = (const uint32_t*)&as[(m + 8) * AROW + kk];
                a[mt][0] = p0[0];  // (m,   kk..kk+1)
                a[mt][1] = p1[0];  // (m+8, kk..kk+1)
                a[mt][2] = p0[4];  // (m,   kk+8..kk+9)
                a[mt][3] = p1[4];  // (m+8, kk+8..kk+9)
            }
            uint32_t b[8][2];
            #pragma unroll
            for (int nt = 0; nt < 8; ++nt) {
                const int n = wn * 64 + nt * 8 + g;
                const uint32_t* pb = (const uint32_t*)&bs[n * AROW + kk];
                b[nt][0] = pb[0];
                b[nt][1] = pb[4];
            }
            #pragma unroll
            for (int mt = 0; mt < 2; ++mt)
                #pragma unroll
                for (int nt = 0; nt < 8; ++nt)
                    mma_f16(acc[mt][nt], a[mt][0], a[mt][1], a[mt][2], a[mt][3],
                            b[nt][0], b[nt][1]);
        }
        __syncthreads();
    }

    // ---- epilogue ----
    #pragma unroll
    for (int mt = 0; mt < 2; ++mt) {
        const int m = bm + wm * 32 + mt * 16 + g;
        #pragma unroll
        for (int nt = 0; nt < 8; ++nt) {
            const int n = bn + wn * 64 + nt * 8 + 2 * t;
            float bx = 0.f, by = 0.f;
            if (bias) { bx = bias[n]; by = bias[n + 1]; }
            const float v0 = acc[mt][nt][0] + bx, v1 = acc[mt][nt][1] + by;
            const float v2 = acc[mt][nt][2] + bx, v3 = acc[mt][nt][3] + by;
            if (OUTH) {
                __half* C = (__half*)Cv + blockIdx.z * sC;
                *(__half2*)(C + (long)m * ldc + n)       = __floats2half2_rn(v0, v1);
                *(__half2*)(C + (long)(m + 8) * ldc + n) = __floats2half2_rn(v2, v3);
            } else {
                float* C = (float*)Cv + blockIdx.z * sC;
                *(float2*)(C + (long)m * ldc + n)       = make_float2(v0, v1);
                *(float2*)(C + (long)(m + 8) * ldc + n) = make_float2(v2, v3);
            }
        }
    }
}

// ---------------------------------------------------------------------------
// Transpose V slices: qkv[slice][key][512+d] -> vt[slice][d][key]  (fp16)
// ---------------------------------------------------------------------------
__global__ __launch_bounds__(256)
void transpose_v(const __half* __restrict__ qkv, __half* __restrict__ vt)
{
    __shared__ __half tile[32][40];
    const int s  = blockIdx.z;
    const __half* src = qkv + (size_t)s * SEQ * QKVN + 2 * DIM;
    __half* dst = vt + (size_t)s * DIM * SEQ;
    const int k0 = blockIdx.x * 32, d0 = blockIdx.y * 32;
    const int tx = threadIdx.x & 31, ty = threadIdx.x >> 5;
    #pragma unroll
    for (int j = 0; j < 4; ++j)
        tile[ty + 8 * j][tx] = src[(size_t)(k0 + ty + 8 * j) * QKVN + d0 + tx];
    __syncthreads();
    #pragma unroll
    for (int j = 0; j < 4; ++j)
        dst[(size_t)(d0 + ty + 8 * j) * SEQ + k0 + tx] = tile[tx][ty + 8 * j];
}

// ---------------------------------------------------------------------------
// Row softmax: fp32 scores in, fp16 probs out. Row cached in registers.
// ---------------------------------------------------------------------------
__global__ __launch_bounds__(256)
void softmax_kernel(const float* __restrict__ S, __half* __restrict__ P, float scale)
{
    const float4* p = (const float4*)(S + (size_t)blockIdx.x * SEQ);
    __half* po = P + (size_t)blockIdx.x * SEQ;
    const int tid = threadIdx.x;
    __shared__ float red[8];

    float4 r[4];
    #pragma unroll
    for (int i = 0; i < 4; ++i) r[i] = p[i * 256 + tid];

    float m = -1e30f;
    #pragma unroll
    for (int i = 0; i < 4; ++i)
        m = fmaxf(m, fmaxf(fmaxf(r[i].x, r[i].y), fmaxf(r[i].z, r[i].w)));
    #pragma unroll
    for (int o = 16; o; o >>= 1) m = fmaxf(m, __shfl_xor_sync(0xffffffffu, m, o));
    if ((tid & 31) == 0) red[tid >> 5] = m;
    __syncthreads();
    m = red[0];
    #pragma unroll
    for (int i = 1; i < 8; ++i) m = fmaxf(m, red[i]);
    __syncthreads();

    float sum = 0.f;
    #pragma unroll
    for (int i = 0; i < 4; ++i) {
        r[i].x = __expf(scale * (r[i].x - m)); sum += r[i].x;
        r[i].y = __expf(scale * (r[i].y - m)); sum += r[i].y;
        r[i].z = __expf(scale * (r[i].z - m)); sum += r[i].z;
        r[i].w = __expf(scale * (r[i].w - m)); sum += r[i].w;
    }
    #pragma unroll
    for (int o = 16; o; o >>= 1) sum += __shfl_xor_sync(0xffffffffu, sum, o);
    if ((tid & 31) == 0) red[tid >> 5] = sum;
    __syncthreads();
    sum = 0.f;
    #pragma unroll
    for (int i = 0; i < 8; ++i) sum += red[i];
    const float inv = 1.f / sum;

    #pragma unroll
    for (int i = 0; i < 4; ++i) {
        const int f = (i * 256 + tid) * 4;
        *(__half2*)(po + f)     = __floats2half2_rn(r[i].x * inv, r[i].y * inv);
        *(__half2*)(po + f + 2) = __floats2half2_rn(r[i].z * inv, r[i].w * inv);
    }
}

// ---------------------------------------------------------------------------
// Round-copy fp32 tokens -> fp16 scratch
// ---------------------------------------------------------------------------
__global__ __launch_bounds__(256)
void round_copy_h(const float* __restrict__ src, __half* __restrict__ dst, int n)
{
    const int i = blockIdx.x * 1024 + threadIdx.x * 4;
    if (i >= n) return;
    float4 v = *(const float4*)(src + i);
    *(__half2*)(dst + i)     = __floats2half2_rn(v.x, v.y);
    *(__half2*)(dst + i + 2) = __floats2half2_rn(v.z, v.w);
}

// ---------------------------------------------------------------------------
// Pack [wq;wk;wv] -> g_wqkv (fp16) and biases -> g_bqkv (fp32)
// ---------------------------------------------------------------------------
__global__ __launch_bounds__(256)
void build_wqkv(const float* __restrict__ wq, const float* __restrict__ wk,
                const float* __restrict__ wv, const float* __restrict__ bq,
                const float* __restrict__ bk, const float* __restrict__ bv,
                __half* __restrict__ W, float* __restrict__ Bb)
{
    const int idx = blockIdx.x * 256 + threadIdx.x;
    if (idx >= QKVN * DIM) return;
    const int r = idx / DIM, c = idx % DIM;
    const float* w = (r < DIM) ? wq : (r < 2 * DIM) ? wk : wv;
    W[idx] = __float2half_rn(w[(r & (DIM - 1)) * DIM + c]);
    if (idx < QKVN) {
        const float* b = (idx < DIM) ? bq : (idx < 2 * DIM) ? bk : bv;
        Bb[idx] = b[idx & (DIM - 1)];
    }
}

// ---------------------------------------------------------------------------
// y = LayerNorm(att + tokens) * g + b -> concatenated x buffer (fp32)
// ---------------------------------------------------------------------------
__global__ __launch_bounds__(256)
void resid_ln_kernel(const float* __restrict__ att, const float* __restrict__ tok,
                     const float* __restrict__ g, const float* __restrict__ b,
                     float* __restrict__ xout, int view)
{
    const long row = blockIdx.x;
    const int d = threadIdx.x;
    __shared__ float red[8];

    const float v = att[row * DIM + d] + tok[row * DIM + d];

    float s = v;
    #pragma unroll
    for (int o = 16; o; o >>= 1) s += __shfl_xor_sync(0xffffffffu, s, o);
    if ((d & 31) == 0) red[d >> 5] = s;
    __syncthreads();
    float mean = 0.f;
    #pragma unroll
    for (int i = 0; i < 8; ++i) mean += red[i];
    mean *= (1.f / DIM);
    __syncthreads();

    const float c = v - mean;
    float s2 = c * c;
    #pragma unroll
    for (int o = 16; o; o >>= 1) s2 += __shfl_xor_sync(0xffffffffu, s2, o);
    if ((d & 31) == 0) red[d >> 5] = s2;
    __syncthreads();
    float var = 0.f;
    #pragma unroll
    for (int i = 0; i < 8; ++i) var += red[i];
    var *= (1.f / DIM);

    const float y = c * rsqrtf(var + 1e-5f) * g[d] + b[d];
    xout[row * IN3 + (long)view * DIM + d] = y;
}

// ---------------------------------------------------------------------------
// Combined weight: [base_w | spline_w * scaler] -> fp16
// ---------------------------------------------------------------------------
__global__ __launch_bounds__(256)
void build_w_kernel(const float* __restrict__ bw, const float* __restrict__ sw,
                    const float* __restrict__ sc, __half* __restrict__ W)
{
    const long idx = (long)blockIdx.x * blockDim.x + threadIdx.x;
    if (idx >= (long)DIM * IN3) return;
    const int o = (int)(idx / IN3);
    const int i = (int)(idx % IN3);
    W[(long)o * KCOMB + i] = __float2half_rn(bw[(long)o * IN3 + i]);
    const float s = sc[(long)o * IN3 + i];
    const float* swp = sw + ((long)o * IN3 + i) * NB;
    __half* wp = W + (long)o * KCOMB + IN3 + (long)i * NB;
    #pragma unroll
    for (int f = 0; f < NB; ++f) wp[f] = __float2half_rn(swp[f] * s);
}

// ---------------------------------------------------------------------------
// Combined A: [silu(x) | cubic b-spline bases] -> fp16
// ---------------------------------------------------------------------------
__global__ __launch_bounds__(256)
void build_a_kernel(const float* __restrict__ x, __half* __restrict__ A)
{
    const long idx = (long)blockIdx.x * blockDim.x + threadIdx.x;
    if (idx >= (long)NROWS * IN3) return;
    const long n = idx / IN3;
    const int i = (int)(idx % IN3);
    const float v = x[idx];

    const float sig = 1.f / (1.f + __expf(-v));
    A[n * KCOMB + i] = __float2half_rn(v * sig);

    const float h = 0.4f;
    float b[11];
    #pragma unroll
    for (int j = 0; j < 11; ++j) {
        const float gj  = -1.f + (j - 3) * h;
        const float gj1 = -1.f + (j - 2) * h;
        b[j] = (v >= gj && v < gj1) ? 1.f : 0.f;
    }
    #pragma unroll
    for (int k = 1; k <= 3; ++k) {
        #pragma unroll
        for (int j = 0; j <= 10 - k; ++j) {
            const float gj   = -1.f + (j - 3) * h;
            const float gjk  = -1.f + (j - 3 + k) * h;
            const float gj1  = -1.f + (j - 2) * h;
            const float gjk1 = -1.f + (j - 2 + k) * h;
            b[j] = (v - gj) / (gjk - gj) * b[j] + (gjk1 - v) / (gjk1 - gj1) * b[j + 1];
        }
    }
    __half* ap = A + n * KCOMB + IN3 + (long)i * NB;
    #pragma unroll
    for (int f = 0; f < NB; ++f) ap[f] = __float2half_rn(b[f]);
}

// ---------------------------------------------------------------------------
// Host launcher
// ---------------------------------------------------------------------------
extern "C" void kernel_launch(void* const* d_in, const int* in_sizes, int n_in,
                              void* d_out, int out_size)
{
    (void)in_sizes; (void)n_in; (void)out_size;

    const float* tok[NVIEW] = {(const float*)d_in[0], (const float*)d_in[1], (const float*)d_in[2]};
    const float* wq = (const float*)d_in[3];
    const float* bq = (const float*)d_in[4];
    const float* wk = (const float*)d_in[5];
    const float* bk = (const float*)d_in[6];
    const float* wv = (const float*)d_in[7];
    const float* bv = (const float*)d_in[8];
    // d_in[9] = view_emb: per-query constant bias -> softmax-invariant -> unused
    const float* lng[NVIEW] = {(const float*)d_in[10], (const float*)d_in[12], (const float*)d_in[14]};
    const float* lnb[NVIEW] = {(const float*)d_in[11], (const float*)d_in[13], (const float*)d_in[15]};
    const float* bw = (const float*)d_in[16];
    const float* sw = (const float*)d_in[17];
    const float* sc = (const float*)d_in[18];

    __half *ptok, *pwqkv, *pqkv, *pvt, *pp, *pa, *pw;
    float *pbqkv, *s, *att, *x;
    cudaGetSymbolAddress((void**)&ptok,  g_tok);
    cudaGetSymbolAddress((void**)&pwqkv, g_wqkv);
    cudaGetSymbolAddress((void**)&pbqkv, g_bqkv);
    cudaGetSymbolAddress((void**)&pqkv,  g_qkv);
    cudaGetSymbolAddress((void**)&pvt,   g_vt);
    cudaGetSymbolAddress((void**)&s,     g_s);
    cudaGetSymbolAddress((void**)&pp,    g_p);
    cudaGetSymbolAddress((void**)&att,   g_att);
    cudaGetSymbolAddress((void**)&x,     g_x);
    cudaGetSymbolAddress((void**)&pa,    g_a);
    cudaGetSymbolAddress((void**)&pw,    g_w);

    const int SMEM = STAGES * STG_H * 2 * (int)sizeof(__half);   // 61440 B
    cudaFuncSetAttribute(hgemm<true>,  cudaFuncAttributeMaxDynamicSharedMemorySize, SMEM);
    cudaFuncSetAttribute(hgemm<false>, cudaFuncAttributeMaxDynamicSharedMemorySize, SMEM);

    const long qkvSlice = (long)SEQ * QKVN;   // A/B slice stride into g_qkv
    const long sStride  = (long)SEQ * SEQ;

    // 0) pack tokens (fp16) and qkv weights
    const int ntok = NROWS * DIM;
    for (int vi = 0; vi < NVIEW; ++vi)
        round_copy_h<<<(ntok + 1023) / 1024, 256>>>(tok[vi], ptok + (long)vi * ntok, ntok);
    build_wqkv<<<(QKVN * DIM + 255) / 256, 256>>>(wq, wk, wv, bq, bk, bv, pwqkv, pbqkv);

    // 1) fused QKV: [24576,768] = tok @ Wqkv^T + bqkv -> fp16
    {
        dim3 grid(QKVN / 128, ROWS3 / 128, 1);
        hgemm<true><<<grid, 256, SMEM>>>(ptok, DIM, pwqkv, DIM, pqkv, QKVN,
                                         DIM, 0, 0, 0, pbqkv);
    }

    // 1b) transpose V slices -> g_vt
    {
        dim3 grid(SEQ / 32, DIM / 32, NVB);
        transpose_v<<<grid, 256>>>(pqkv, pvt);
    }

    // 2) scores = Q @ K^T (fp32 out), all 6 slices
    {
        dim3 grid(SEQ / 128, SEQ / 128, NVB);
        hgemm<false><<<grid, 256, SMEM>>>(pqkv, QKVN, pqkv + DIM, QKVN, s, SEQ,
                                          DIM, qkvSlice, qkvSlice, sStride, nullptr);
    }

    // 3) softmax(scores / 16) -> fp16 probs
    softmax_kernel<<<NVB * SEQ, 256>>>(s, pp, 0.0625f);

    // 4) att = P @ Vt^T (NT, fp32 out)
    {
        dim3 grid(DIM / 128, SEQ / 128, NVB);
        hgemm<false><<<grid, 256, SMEM>>>(pp, SEQ, pvt, SEQ, att, DIM,
                                          SEQ, sStride, (long)DIM * SEQ, (long)SEQ * DIM, nullptr);
    }

    // 5) LayerNorm(att + tokens) -> concat x (fp32)
    for (int vi = 0; vi < NVIEW; ++vi)
        resid_ln_kernel<<<NROWS, 256>>>(att + (long)vi * NROWS * DIM, tok[vi],
                                        lng[vi], lnb[vi], x, vi);

    // 6) combined weight / combined A (fp16)
    build_w_kernel<<<(DIM * IN3 + 255) / 256, 256>>>(bw, sw, sc, pw);
    build_a_kernel<<<(int)(((long)NROWS * IN3 + 255) / 256), 256>>>(x, pa);

    // 7) out = A @ W^T (base + spline fused, K = 6912, fp32 out)
    {
        dim3 grid(DIM / 128, NROWS / 128, 1);
        hgemm<false><<<grid, 256, SMEM>>>(pa, KCOMB, pw, KCOMB, (float*)d_out, DIM,
                                          KCOMB, 0, 0, 0, nullptr);
    }
}